// round 1
// baseline (speedup 1.0000x reference)
#include <cuda_runtime.h>
#include <cuda_bf16.h>

#define TLEN 2048
#define H 20

// tanh without overflow: tanh(z) = sign(z) * (1 - e) / (1 + e), e = exp(-2|z|) in (0,1]
__device__ __forceinline__ float fast_tanh(float z) {
    float a = fabsf(z);
    float e = __expf(-2.0f * a);
    float r = __fdividef(1.0f - e, 1.0f + e);
    return copysignf(r, z);
}

// 4 threads per batch element ("quad"). Lane q in [0,4) owns hidden rows [5q, 5q+5).
// Per step: 5 input-proj FMA + 100 recurrence FMA + 5 tanh per thread,
// then 20 __shfl_sync to rebuild the full h[20] in every lane.
// Block = 64 threads = 16 batches. Grid = B/16 = 1024 blocks; launch_bounds(64,7)
// keeps 7 blocks/SM resident -> 1036 slots >= 1024 blocks -> single balanced wave.
__global__ void __launch_bounds__(64, 7) rnn_kernel(
    const float* __restrict__ x,      // [B, TLEN] (I=1 squeezed)
    const float* __restrict__ W_ih,   // [H, 1]
    const float* __restrict__ W_hh,   // [H, H]
    const float* __restrict__ b_ih,   // [H]
    const float* __restrict__ b_hh,   // [H]
    const float* __restrict__ W_fc,   // [1, H]
    const float* __restrict__ b_fc,   // [1]
    float* __restrict__ out)          // [B]
{
    __shared__ float sW[H][H];   // W_hh row-major; rows are 80B (16B aligned)
    __shared__ float sWih[H];
    __shared__ float sPre[H];    // b_ih + b_hh
    __shared__ float sWfc[H];
    __shared__ float sBfc;

    const int tid = threadIdx.x;
    for (int i = tid; i < H * H; i += 64) sW[i / H][i % H] = W_hh[i];
    if (tid < H) {
        sWih[tid] = W_ih[tid];
        sPre[tid] = b_ih[tid] + b_hh[tid];
        sWfc[tid] = W_fc[tid];
    }
    if (tid == 0) sBfc = b_fc[0];
    __syncthreads();

    const int lane  = tid & 31;
    const int q     = lane & 3;        // output slice within quad
    const int pbase = lane & ~3;       // quad leader lane
    const int batch = blockIdx.x * 16 + (tid >> 2);

    float wih[5], pre[5];
    #pragma unroll
    for (int i = 0; i < 5; i++) {
        wih[i] = sWih[5 * q + i];
        pre[i] = sPre[5 * q + i];
    }

    float h[H];
    #pragma unroll
    for (int j = 0; j < H; j++) h[j] = 0.0f;

    const float* xp = x + (size_t)batch * TLEN;
    float4 xv = *(const float4*)xp;    // prefetched x[t..t+3]

    for (int t = 0; t < TLEN; t += 4) {
        float4 xn;
        if (t + 4 < TLEN) xn = *(const float4*)(xp + t + 4);  // prefetch next
        float xs[4] = {xv.x, xv.y, xv.z, xv.w};

        #pragma unroll
        for (int s = 0; s < 4; s++) {
            float m[5];
            #pragma unroll
            for (int i = 0; i < 5; i++) {
                float a = fmaf(xs[s], wih[i], pre[i]);
                const float* wrow = sW[5 * q + i];
                #pragma unroll
                for (int k = 0; k < 5; k++) {
                    float4 w = *(const float4*)(wrow + 4 * k);
                    a = fmaf(w.x, h[4 * k + 0], a);
                    a = fmaf(w.y, h[4 * k + 1], a);
                    a = fmaf(w.z, h[4 * k + 2], a);
                    a = fmaf(w.w, h[4 * k + 3], a);
                }
                m[i] = fast_tanh(a);
            }
            // rebuild full h[20] in every lane of the quad (20 shuffles)
            #pragma unroll
            for (int s2 = 0; s2 < 4; s2++) {
                #pragma unroll
                for (int v = 0; v < 5; v++) {
                    h[5 * s2 + v] = __shfl_sync(0xffffffffu, m[v], pbase + s2, 32);
                }
            }
        }
        xv = xn;
    }

    if (q == 0) {
        float acc = sBfc;
        #pragma unroll
        for (int j = 0; j < H; j++) acc = fmaf(h[j], sWfc[j], acc);
        out[batch] = __fdividef(1.0f, 1.0f + __expf(-acc));
    }
}

extern "C" void kernel_launch(void* const* d_in, const int* in_sizes, int n_in,
                              void* d_out, int out_size) {
    const float* x    = (const float*)d_in[0];
    const float* W_ih = (const float*)d_in[1];
    const float* W_hh = (const float*)d_in[2];
    const float* b_ih = (const float*)d_in[3];
    const float* b_hh = (const float*)d_in[4];
    const float* W_fc = (const float*)d_in[5];
    const float* b_fc = (const float*)d_in[6];
    float* out = (float*)d_out;

    const int B = in_sizes[0] / TLEN;      // 16384
    const int blocks = B / 16;             // 1024 (64 threads = 16 quads/block)
    rnn_kernel<<<blocks, 64>>>(x, W_ih, W_hh, b_ih, b_hh, W_fc, b_fc, out);
}

// round 2
// speedup vs baseline: 1.1196x; 1.1196x over previous
#include <cuda_runtime.h>
#include <cuda_bf16.h>

#define TLEN 2048
#define H 20
typedef unsigned long long ull;

// ---- packed f32x2 helpers (sm_103a 2x FP32 path) ----
__device__ __forceinline__ ull pk(float lo, float hi) {
    ull r; asm("mov.b64 %0, {%1, %2};" : "=l"(r) : "f"(lo), "f"(hi)); return r;
}
__device__ __forceinline__ float2 upk(ull v) {
    float2 f; asm("mov.b64 {%0, %1}, %2;" : "=f"(f.x), "=f"(f.y) : "l"(v)); return f;
}
__device__ __forceinline__ ull fma2(ull a, ull b, ull c) {
    ull d; asm("fma.rn.f32x2 %0, %1, %2, %3;" : "=l"(d) : "l"(a), "l"(b), "l"(c)); return d;
}
__device__ __forceinline__ ull mul2(ull a, ull b) {
    ull d; asm("mul.rn.f32x2 %0, %1, %2;" : "=l"(d) : "l"(a), "l"(b)); return d;
}
__device__ __forceinline__ ull add2(ull a, ull b) {
    ull d; asm("add.rn.f32x2 %0, %1, %2;" : "=l"(d) : "l"(a), "l"(b)); return d;
}

// Input z is PRE-SCALED by 2*log2(e): tanh(a) = 1 - 2/(exp2(2*log2e*a) + 1).
// |a| <= ~6 so exp2 arg in [-17,17]: no overflow, no sign handling needed.
__device__ __forceinline__ float tanh_ps(float z) {
    float e; asm("ex2.approx.f32 %0, %1;" : "=f"(e) : "f"(z));
    float r; asm("rcp.approx.f32 %0, %1;" : "=f"(r) : "f"(e + 1.0f));
    return fmaf(-2.0f, r, 1.0f);
}
__device__ __forceinline__ ull tanh2_ps(ull z) {
    float2 f = upk(z);
    return pk(tanh_ps(f.x), tanh_ps(f.y));
}
__device__ __forceinline__ float sigmoid1(float z) {
    float e; asm("ex2.approx.f32 %0, %1;" : "=f"(e) : "f"(z * -1.4426950408889634f));
    float r; asm("rcp.approx.f32 %0, %1;" : "=f"(r) : "f"(e + 1.0f));
    return r;
}

#define KREG 10   // W columns 0..KREG-1 held in registers (packed), rest from smem

// One warp per block. 8 groups of 4 threads; each group owns a BATCH PAIR
// (2 batches packed as f32x2). Thread q in [0,4) owns hidden rows [5q,5q+5).
// Per step/thread: 5 rows x (1 + 20) packed FMAs (2 chains + combine), packed
// tanh (EX2+ADD+RCP+FMA per scalar, weights pre-scaled by 2*log2e), then 30
// SHFL to rebuild full packed h[20]. 1024 blocks -> 6-7 warps/SM, one wave.
__global__ void __launch_bounds__(32) rnn_kernel(
    const float* __restrict__ x,      // [B, TLEN]
    const float* __restrict__ W_ih,   // [H]
    const float* __restrict__ W_hh,   // [H, H]
    const float* __restrict__ b_ih,   // [H]
    const float* __restrict__ b_hh,   // [H]
    const float* __restrict__ W_fc,   // [H]
    const float* __restrict__ b_fc,   // [1]
    float* __restrict__ out)          // [B]
{
    __shared__ __align__(16) float2 sW2[H][H];  // (w,w) pairs, pre-scaled
    __shared__ float2 sWih2[H], sPre2[H];
    __shared__ float  sWfc[H];
    __shared__ float  sBfc;

    const int tid = threadIdx.x;
    const float SC = 2.8853900817779268f;  // 2*log2(e)

    for (int i = tid; i < H * H; i += 32) {
        float w = W_hh[i] * SC;
        sW2[i / H][i % H] = make_float2(w, w);
    }
    if (tid < H) {
        float wi = W_ih[tid] * SC;
        sWih2[tid] = make_float2(wi, wi);
        float p = (b_ih[tid] + b_hh[tid]) * SC;
        sPre2[tid] = make_float2(p, p);
        sWfc[tid] = W_fc[tid];
    }
    if (tid == 0) sBfc = b_fc[0];
    __syncthreads();

    const int q     = tid & 3;
    const int pbase = tid & ~3;
    const int gp    = blockIdx.x * 8 + (tid >> 2);   // batch-pair index
    const int b0    = 2 * gp;

    // Register-resident packed weights: rows 5q..5q+4, cols 0..KREG-1
    ull wr[5][KREG];
    ull wih2[5], pre2[5];
    #pragma unroll
    for (int i = 0; i < 5; i++) {
        const int r = 5 * q + i;
        #pragma unroll
        for (int c = 0; c < KREG; c++)
            wr[i][c] = *(const ull*)&sW2[r][c];
        wih2[i] = *(const ull*)&sWih2[r];
        pre2[i] = *(const ull*)&sPre2[r];
    }

    ull h[H];
    #pragma unroll
    for (int j = 0; j < H; j++) h[j] = 0ull;

    const float* xa = x + (size_t)b0 * TLEN;
    const float* xb = xa + TLEN;
    float4 va = *(const float4*)xa;
    float4 vb = *(const float4*)xb;

    for (int t = 0; t < TLEN; t += 4) {
        float4 na, nb;
        if (t + 4 < TLEN) {
            na = *(const float4*)(xa + t + 4);
            nb = *(const float4*)(xb + t + 4);
        }
        const float as[4] = {va.x, va.y, va.z, va.w};
        const float bs[4] = {vb.x, vb.y, vb.z, vb.w};

        #pragma unroll
        for (int s = 0; s < 4; s++) {
            const ull x2 = pk(as[s], bs[s]);
            ull m[5];
            #pragma unroll
            for (int i = 0; i < 5; i++) {
                const int r = 5 * q + i;
                // chain A: input proj + h[0..KREG-1] from registers
                ull a = fma2(x2, wih2[i], pre2[i]);
                #pragma unroll
                for (int c = 0; c < KREG; c++)
                    a = fma2(wr[i][c], h[c], a);
                // chain B: h[KREG..19] from shared (5x LDS.128, 16B aligned)
                const ull* wp = (const ull*)&sW2[r][KREG];
                ull b = mul2(wp[0], h[KREG]);
                #pragma unroll
                for (int c = 1; c < H - KREG; c++)
                    b = fma2(wp[c], h[KREG + c], b);
                m[i] = tanh2_ps(add2(a, b));
            }
            // rebuild full packed h[20] across the quad (30 SHFL)
            #pragma unroll
            for (int s2 = 0; s2 < 4; s2++) {
                #pragma unroll
                for (int v = 0; v < 5; v++)
                    h[5 * s2 + v] = __shfl_sync(0xffffffffu, m[v], pbase + s2, 32);
            }
        }
        va = na; vb = nb;
    }

    if (q == 0) {
        ull acc = pk(sBfc, sBfc);
        #pragma unroll
        for (int j = 0; j < H; j++)
            acc = fma2(h[j], pk(sWfc[j], sWfc[j]), acc);
        float2 y = upk(acc);
        out[b0]     = sigmoid1(y.x);
        out[b0 + 1] = sigmoid1(y.y);
    }
}

extern "C" void kernel_launch(void* const* d_in, const int* in_sizes, int n_in,
                              void* d_out, int out_size) {
    const float* x    = (const float*)d_in[0];
    const float* W_ih = (const float*)d_in[1];
    const float* W_hh = (const float*)d_in[2];
    const float* b_ih = (const float*)d_in[3];
    const float* b_hh = (const float*)d_in[4];
    const float* W_fc = (const float*)d_in[5];
    const float* b_fc = (const float*)d_in[6];
    float* out = (float*)d_out;

    const int B = in_sizes[0] / TLEN;   // 16384
    const int blocks = B / 16;          // 16 batches (8 pairs) per 32-thread block
    rnn_kernel<<<blocks, 32>>>(x, W_ih, W_hh, b_ih, b_hh, W_fc, b_fc, out);
}